// round 14
// baseline (speedup 1.0000x reference)
#include <cuda_runtime.h>
#include <cuda_bf16.h>
#include <cstdint>

#define NN 50000
#define EE 800000
#define CAP 128           // deg ~ Poisson(16), max ~50 << 128
#define NT  391           // ceil(NN/128) tiles

// smem: 2 B planes, 128 rows x 136 bf16 (272B pitch -> conflict-free frags)
#define PITCHW 68         // 32-bit words per row
#define PLANE  34816      // 128 * 272 bytes
#define SM_BH  0
#define SM_BL  (PLANE)
#define SMEM_BYTES (2 * PLANE)   // 69632

// ---------------- scratch (device globals; no allocation allowed) ------------
__device__ int      g_cnt[NN];
__device__ float    g_dinv[NN];
__device__ float4   g_h[NN * 32];         // h = x @ W_gcn (UNSCALED)
__device__ float4   g_agg[NN * 32];       // relu(agg + b_gcn)
__device__ int      g_bucket[NN * CAP];
__device__ uint32_t g_Bg_hi[8192], g_Bg_lo[8192];  // W_gcn^T [n][k-pairs] bf16x2
__device__ uint32_t g_B1_hi[8192], g_B1_lo[8192];  // W1^T    [n][k-pairs] bf16x2

// ---------------- helpers -------------------------------------------------------
__device__ __forceinline__ uint32_t pack_bf2(__nv_bfloat16 lo, __nv_bfloat16 hi) {
    return ((uint32_t)__bfloat16_as_ushort(hi) << 16) | (uint32_t)__bfloat16_as_ushort(lo);
}
__device__ __forceinline__ void split2(float a0, float a1, uint32_t& phi, uint32_t& plo) {
    __nv_bfloat16 h0 = __float2bfloat16_rn(a0);
    __nv_bfloat16 h1 = __float2bfloat16_rn(a1);
    __nv_bfloat16 l0 = __float2bfloat16_rn(a0 - __bfloat162float(h0));
    __nv_bfloat16 l1 = __float2bfloat16_rn(a1 - __bfloat162float(h1));
    phi = pack_bf2(h0, h1);
    plo = pack_bf2(l0, l1);
}
__device__ __forceinline__ void mma16816(float* c, const uint32_t* a,
                                         uint32_t b0, uint32_t b1) {
    asm volatile(
        "mma.sync.aligned.m16n8k16.row.col.f32.bf16.bf16.f32 "
        "{%0,%1,%2,%3}, {%4,%5,%6,%7}, {%8,%9}, {%0,%1,%2,%3};"
        : "+f"(c[0]), "+f"(c[1]), "+f"(c[2]), "+f"(c[3])
        : "r"(a[0]), "r"(a[1]), "r"(a[2]), "r"(a[3]), "r"(b0), "r"(b1));
}

// ---------------- bucket build ---------------------------------------------------
__global__ void k_init() {
    int i = blockIdx.x * blockDim.x + threadIdx.x;
    if (i < NN) g_cnt[i] = 0;
}

__global__ void k_fill(const int* __restrict__ ei) {
    int e4 = blockIdx.x * blockDim.x + threadIdx.x;
    if (e4 >= EE / 4) return;
    int4 s = ((const int4*)ei)[e4];
    int4 d = ((const int4*)(ei + EE))[e4];
    int p;
    p = atomicAdd(&g_cnt[d.x], 1); if (p < CAP) g_bucket[d.x * CAP + p] = s.x;
    p = atomicAdd(&g_cnt[d.y], 1); if (p < CAP) g_bucket[d.y * CAP + p] = s.y;
    p = atomicAdd(&g_cnt[d.z], 1); if (p < CAP) g_bucket[d.z * CAP + p] = s.z;
    p = atomicAdd(&g_cnt[d.w], 1); if (p < CAP) g_bucket[d.w * CAP + p] = s.w;
}

__global__ void k_dinv() {
    int i = blockIdx.x * blockDim.x + threadIdx.x;
    if (i < NN) g_dinv[i] = rsqrtf((float)(g_cnt[i] + 1));
}

// ---------------- W split (coalesced reads, scattered 4B writes) -----------------
__global__ void k_splitw(const float* __restrict__ Wg, const float* __restrict__ W1) {
    int idx = blockIdx.x * blockDim.x + threadIdx.x;
    if (idx >= 8192) return;
    int n   = idx & 127;      // fastest -> coalesced gmem reads
    int kpi = idx >> 7;       // 0..63
    int kp  = kpi * 2;
    int o   = n * 64 + kpi;
    uint32_t phi, plo;
    split2(Wg[kp * 128 + n], Wg[(kp + 1) * 128 + n], phi, plo);
    g_Bg_hi[o] = phi; g_Bg_lo[o] = plo;
    split2(W1[kp * 128 + n], W1[(kp + 1) * 128 + n], phi, plo);
    g_B1_hi[o] = phi; g_B1_lo[o] = plo;
}

// ---------------- B planes -> smem --------------------------------------------------
__device__ __forceinline__ void load_B(char* smem, const uint32_t* __restrict__ bh,
                                       const uint32_t* __restrict__ bl, int tid) {
    uint32_t* BH = (uint32_t*)(smem + SM_BH);
    uint32_t* BL = (uint32_t*)(smem + SM_BL);
    #pragma unroll
    for (int i = tid; i < 8192; i += 256) {
        int n = i >> 6, w = i & 63;
        BH[n * PITCHW + w] = bh[n * 64 + w];
        BL[n * PITCHW + w] = bl[n * 64 + w];
    }
}

// 3-pass split mma. A straight from gmem (per-thread frag addresses), split in
// registers; B hi/lo from smem. acc[16][4]; warp = rows [wid*16, wid*16+16).
// unroll 1 on ks keeps live ranges minimal for the 3-CTA register budget.
__device__ __forceinline__ void run_mma_g(char* smem, const float* __restrict__ src,
                                          int row0, float acc[16][4],
                                          int wid, int lane) {
    const uint32_t* BH = (const uint32_t*)(smem + SM_BH);
    const uint32_t* BL = (const uint32_t*)(smem + SM_BL);
    const int gid = lane >> 2;
    const int tig = lane & 3;
    const int rA  = wid * 16 + gid;
    const int gr0 = row0 + rA;
    const int gr1 = gr0 + 8;
    const float* p0 = src + (size_t)(gr0 < NN ? gr0 : row0) * 128;
    const float* p1 = src + (size_t)(gr1 < NN ? gr1 : row0) * 128;

    #pragma unroll 1
    for (int ks = 0; ks < 8; ++ks) {
        const int kw = ks * 8 + tig;
        float2 x0 = *(const float2*)(p0 + 2 * kw);
        float2 x1 = *(const float2*)(p1 + 2 * kw);
        float2 x2 = *(const float2*)(p0 + 2 * kw + 8);
        float2 x3 = *(const float2*)(p1 + 2 * kw + 8);
        uint32_t ah[4], al[4];
        split2(x0.x, x0.y, ah[0], al[0]);
        split2(x1.x, x1.y, ah[1], al[1]);
        split2(x2.x, x2.y, ah[2], al[2]);
        split2(x3.x, x3.y, ah[3], al[3]);
        #pragma unroll
        for (int nf = 0; nf < 16; ++nf) {
            int nB = nf * 8 + gid;
            uint32_t bh0 = BH[nB * PITCHW + kw];
            uint32_t bh1 = BH[nB * PITCHW + kw + 4];
            uint32_t bl0 = BL[nB * PITCHW + kw];
            uint32_t bl1 = BL[nB * PITCHW + kw + 4];
            mma16816(acc[nf], ah, bh0, bh1);
            mma16816(acc[nf], ah, bl0, bl1);
            mma16816(acc[nf], al, bh0, bh1);
        }
    }
}

// ---------------- GEMM1 (tensor): h = x @ W_gcn (unscaled) -----------------------
__global__ void __launch_bounds__(256, 3) k_gemm1_tc(const float* __restrict__ x) {
    extern __shared__ char smem[];
    const int tid = threadIdx.x, wid = tid >> 5, lane = tid & 31;
    const int row0 = blockIdx.x * 128;

    load_B(smem, g_Bg_hi, g_Bg_lo, tid);
    __syncthreads();

    float acc[16][4];
    #pragma unroll
    for (int i = 0; i < 16; ++i)
        acc[i][0] = acc[i][1] = acc[i][2] = acc[i][3] = 0.f;
    run_mma_g(smem, x, row0, acc, wid, lane);

    const int gid = lane >> 2, tig = lane & 3;
    int gr0 = row0 + wid * 16 + gid;
    int gr1 = gr0 + 8;
    float* hf = (float*)g_h;
    #pragma unroll
    for (int nf = 0; nf < 16; ++nf) {
        int c = nf * 8 + tig * 2;
        if (gr0 < NN)
            *(float2*)(hf + (size_t)gr0 * 128 + c) = make_float2(acc[nf][0], acc[nf][1]);
        if (gr1 < NN)
            *(float2*)(hf + (size_t)gr1 * 128 + c) = make_float2(acc[nf][2], acc[nf][3]);
    }
}

// ---------------- gather: agg[d] = relu(dv_d*(dv_d*h[d] + sum dv_s*h[s]) + bg) ---
__global__ void __launch_bounds__(256) k_gather(const float* __restrict__ bg) {
    int gw   = (blockIdx.x * blockDim.x + threadIdx.x) >> 5;
    int lane = threadIdx.x & 31;
    if (gw >= NN) return;
    const int d = gw;

    int deg = g_cnt[d];
    float dv_d = g_dinv[d];
    if (deg > CAP) deg = CAP;

    float4 hd = g_h[d * 32 + lane];
    float4 a0, a1;
    a0.x = hd.x * dv_d; a0.y = hd.y * dv_d; a0.z = hd.z * dv_d; a0.w = hd.w * dv_d;
    a1 = make_float4(0.f, 0.f, 0.f, 0.f);

    const int* bkt = &g_bucket[d * CAP];
    for (int j0 = 0; j0 < deg; j0 += 32) {
        int myi = j0 + lane;
        int   s  = (myi < deg) ? bkt[myi] : 0;
        float nm = (myi < deg) ? g_dinv[s] : 0.f;
        int cnt = deg - j0; if (cnt > 32) cnt = 32;
        int t = 0;
        for (; t + 4 <= cnt; t += 4) {
            int s0 = __shfl_sync(0xFFFFFFFFu, s, t);
            int s1 = __shfl_sync(0xFFFFFFFFu, s, t + 1);
            int s2 = __shfl_sync(0xFFFFFFFFu, s, t + 2);
            int s3 = __shfl_sync(0xFFFFFFFFu, s, t + 3);
            float n0 = __shfl_sync(0xFFFFFFFFu, nm, t);
            float n1 = __shfl_sync(0xFFFFFFFFu, nm, t + 1);
            float n2 = __shfl_sync(0xFFFFFFFFu, nm, t + 2);
            float n3 = __shfl_sync(0xFFFFFFFFu, nm, t + 3);
            float4 v0 = g_h[s0 * 32 + lane];
            float4 v1 = g_h[s1 * 32 + lane];
            float4 v2 = g_h[s2 * 32 + lane];
            float4 v3 = g_h[s3 * 32 + lane];
            a0.x = fmaf(v0.x, n0, a0.x); a0.y = fmaf(v0.y, n0, a0.y);
            a0.z = fmaf(v0.z, n0, a0.z); a0.w = fmaf(v0.w, n0, a0.w);
            a1.x = fmaf(v1.x, n1, a1.x); a1.y = fmaf(v1.y, n1, a1.y);
            a1.z = fmaf(v1.z, n1, a1.z); a1.w = fmaf(v1.w, n1, a1.w);
            a0.x = fmaf(v2.x, n2, a0.x); a0.y = fmaf(v2.y, n2, a0.y);
            a0.z = fmaf(v2.z, n2, a0.z); a0.w = fmaf(v2.w, n2, a0.w);
            a1.x = fmaf(v3.x, n3, a1.x); a1.y = fmaf(v3.y, n3, a1.y);
            a1.z = fmaf(v3.z, n3, a1.z); a1.w = fmaf(v3.w, n3, a1.w);
        }
        for (; t < cnt; ++t) {
            int   ss = __shfl_sync(0xFFFFFFFFu, s, t);
            float nn = __shfl_sync(0xFFFFFFFFu, nm, t);
            float4 v = g_h[ss * 32 + lane];
            a0.x = fmaf(v.x, nn, a0.x); a0.y = fmaf(v.y, nn, a0.y);
            a0.z = fmaf(v.z, nn, a0.z); a0.w = fmaf(v.w, nn, a0.w);
        }
    }
    a0.x += a1.x; a0.y += a1.y; a0.z += a1.z; a0.w += a1.w;

    float4 bgv = __ldg(&((const float4*)bg)[lane]);
    float4 r;
    r.x = fmaxf(fmaf(a0.x, dv_d, bgv.x), 0.f);
    r.y = fmaxf(fmaf(a0.y, dv_d, bgv.y), 0.f);
    r.z = fmaxf(fmaf(a0.z, dv_d, bgv.z), 0.f);
    r.w = fmaxf(fmaf(a0.w, dv_d, bgv.w), 0.f);
    g_agg[d * 32 + lane] = r;
}

// ---------------- MLP (tensor): out = relu(agg @ W1 + b1) . W2 + b2 --------------
__global__ void __launch_bounds__(256, 3) k_mlp_tc(const float* __restrict__ b1,
                                                   const float* __restrict__ W2,
                                                   const float* __restrict__ b2,
                                                   float* __restrict__ out) {
    extern __shared__ char smem[];
    const int tid = threadIdx.x, wid = tid >> 5, lane = tid & 31;
    const int row0 = blockIdx.x * 128;

    load_B(smem, g_B1_hi, g_B1_lo, tid);
    __syncthreads();

    float acc[16][4];
    #pragma unroll
    for (int i = 0; i < 16; ++i)
        acc[i][0] = acc[i][1] = acc[i][2] = acc[i][3] = 0.f;
    run_mma_g(smem, (const float*)g_agg, row0, acc, wid, lane);

    float sumA = 0.f, sumB = 0.f;
    const int cb = (lane & 3) * 2;
    #pragma unroll
    for (int nf = 0; nf < 16; ++nf) {
        int c = nf * 8 + cb;
        float bb0 = __ldg(b1 + c), bb1 = __ldg(b1 + c + 1);
        float w0  = __ldg(W2 + c), w1  = __ldg(W2 + c + 1);
        sumA = fmaf(fmaxf(acc[nf][0] + bb0, 0.f), w0, sumA);
        sumA = fmaf(fmaxf(acc[nf][1] + bb1, 0.f), w1, sumA);
        sumB = fmaf(fmaxf(acc[nf][2] + bb0, 0.f), w0, sumB);
        sumB = fmaf(fmaxf(acc[nf][3] + bb1, 0.f), w1, sumB);
    }
    sumA += __shfl_xor_sync(0xFFFFFFFFu, sumA, 1);
    sumA += __shfl_xor_sync(0xFFFFFFFFu, sumA, 2);
    sumB += __shfl_xor_sync(0xFFFFFFFFu, sumB, 1);
    sumB += __shfl_xor_sync(0xFFFFFFFFu, sumB, 2);

    if ((lane & 3) == 0) {
        float b2s = __ldg(b2);
        int r = row0 + wid * 16 + (lane >> 2);
        if (r < NN)     out[r]     = sumA + b2s;
        if (r + 8 < NN) out[r + 8] = sumB + b2s;
    }
}

// ---------------- launch -----------------------------------------------------------
extern "C" void kernel_launch(void* const* d_in, const int* in_sizes, int n_in,
                              void* d_out, int out_size) {
    const float* x  = (const float*)d_in[0];
    const int*   ei = (const int*)  d_in[1];
    const float* Wg = (const float*)d_in[2];
    const float* bg = (const float*)d_in[3];
    const float* W1 = (const float*)d_in[4];
    const float* b1 = (const float*)d_in[5];
    const float* W2 = (const float*)d_in[6];
    const float* b2 = (const float*)d_in[7];
    float* out = (float*)d_out;

    cudaFuncSetAttribute(k_gemm1_tc, cudaFuncAttributeMaxDynamicSharedMemorySize, SMEM_BYTES);
    cudaFuncSetAttribute(k_mlp_tc,   cudaFuncAttributeMaxDynamicSharedMemorySize, SMEM_BYTES);

    // streams/events created once on the first (non-captured) correctness call
    static cudaStream_t s1 = nullptr;
    static cudaEvent_t  evF = nullptr, evJ = nullptr;
    if (s1 == nullptr) {
        if (cudaStreamCreateWithFlags(&s1, cudaStreamNonBlocking) != cudaSuccess) s1 = nullptr;
        if (s1 && cudaEventCreateWithFlags(&evF, cudaEventDisableTiming) != cudaSuccess) { evF = nullptr; }
        if (s1 && evF && cudaEventCreateWithFlags(&evJ, cudaEventDisableTiming) != cudaSuccess) { evJ = nullptr; }
    }
    const bool par = (s1 != nullptr) && (evF != nullptr) && (evJ != nullptr);

    if (par) {
        cudaEventRecord(evF, 0);
        cudaStreamWaitEvent(s1, evF, 0);
        k_init<<<(NN + 255) / 256, 256, 0, s1>>>();
        k_fill<<<(EE / 4 + 255) / 256, 256, 0, s1>>>(ei);
        k_dinv<<<(NN + 255) / 256, 256, 0, s1>>>();
        cudaEventRecord(evJ, s1);
        k_splitw  <<<32, 256>>>(Wg, W1);
        k_gemm1_tc<<<NT, 256, SMEM_BYTES>>>(x);
        cudaStreamWaitEvent(0, evJ, 0);
    } else {
        k_init    <<<(NN + 255) / 256, 256>>>();
        k_fill    <<<(EE / 4 + 255) / 256, 256>>>(ei);
        k_dinv    <<<(NN + 255) / 256, 256>>>();
        k_splitw  <<<32, 256>>>(Wg, W1);
        k_gemm1_tc<<<NT, 256, SMEM_BYTES>>>(x);
    }

    k_gather<<<(NN * 32 + 255) / 256, 256>>>(bg);
    k_mlp_tc<<<NT, 256, SMEM_BYTES>>>(b1, W2, b2, out);
}

// round 15
// speedup vs baseline: 1.0463x; 1.0463x over previous
#include <cuda_runtime.h>
#include <cuda_bf16.h>
#include <cstdint>

#define NN 50000
#define EE 800000
#define CAP 128           // deg ~ Poisson(16), max ~50 << 128
#define NT  391           // ceil(NN/128) tiles
#define GRID_P 296        // persistent grid: 2 CTAs/SM x 148 SMs

// smem: 2 B planes, 128 rows x 136 bf16 (272B pitch -> conflict-free frags)
#define PITCHW 68         // 32-bit words per row
#define PLANE  34816      // 128 * 272 bytes
#define SM_BH  0
#define SM_BL  (PLANE)
#define SMEM_BYTES (2 * PLANE)   // 69632

// ---------------- scratch (device globals; no allocation allowed) ------------
__device__ int      g_cnt[NN];
__device__ float    g_dinv[NN];
__device__ float4   g_h[NN * 32];         // h = x @ W_gcn (UNSCALED)
__device__ float4   g_agg[NN * 32];       // relu(agg + b_gcn)
__device__ int      g_bucket[NN * CAP];
__device__ uint32_t g_Bg_hi[8192], g_Bg_lo[8192];  // W_gcn^T [n][k-pairs] bf16x2
__device__ uint32_t g_B1_hi[8192], g_B1_lo[8192];  // W1^T    [n][k-pairs] bf16x2

// ---------------- helpers -------------------------------------------------------
__device__ __forceinline__ uint32_t pack_bf2(__nv_bfloat16 lo, __nv_bfloat16 hi) {
    return ((uint32_t)__bfloat16_as_ushort(hi) << 16) | (uint32_t)__bfloat16_as_ushort(lo);
}
__device__ __forceinline__ void split2(float a0, float a1, uint32_t& phi, uint32_t& plo) {
    __nv_bfloat16 h0 = __float2bfloat16_rn(a0);
    __nv_bfloat16 h1 = __float2bfloat16_rn(a1);
    __nv_bfloat16 l0 = __float2bfloat16_rn(a0 - __bfloat162float(h0));
    __nv_bfloat16 l1 = __float2bfloat16_rn(a1 - __bfloat162float(h1));
    phi = pack_bf2(h0, h1);
    plo = pack_bf2(l0, l1);
}
__device__ __forceinline__ void mma16816(float* c, const uint32_t* a,
                                         uint32_t b0, uint32_t b1) {
    asm volatile(
        "mma.sync.aligned.m16n8k16.row.col.f32.bf16.bf16.f32 "
        "{%0,%1,%2,%3}, {%4,%5,%6,%7}, {%8,%9}, {%0,%1,%2,%3};"
        : "+f"(c[0]), "+f"(c[1]), "+f"(c[2]), "+f"(c[3])
        : "r"(a[0]), "r"(a[1]), "r"(a[2]), "r"(a[3]), "r"(b0), "r"(b1));
}

// ---------------- bucket build ---------------------------------------------------
__global__ void k_init() {
    int i = blockIdx.x * blockDim.x + threadIdx.x;
    if (i < NN) g_cnt[i] = 0;
}

__global__ void k_fill(const int* __restrict__ ei) {
    int e4 = blockIdx.x * blockDim.x + threadIdx.x;
    if (e4 >= EE / 4) return;
    int4 s = ((const int4*)ei)[e4];
    int4 d = ((const int4*)(ei + EE))[e4];
    int p;
    p = atomicAdd(&g_cnt[d.x], 1); if (p < CAP) g_bucket[d.x * CAP + p] = s.x;
    p = atomicAdd(&g_cnt[d.y], 1); if (p < CAP) g_bucket[d.y * CAP + p] = s.y;
    p = atomicAdd(&g_cnt[d.z], 1); if (p < CAP) g_bucket[d.z * CAP + p] = s.z;
    p = atomicAdd(&g_cnt[d.w], 1); if (p < CAP) g_bucket[d.w * CAP + p] = s.w;
}

__global__ void k_dinv() {
    int i = blockIdx.x * blockDim.x + threadIdx.x;
    if (i < NN) g_dinv[i] = rsqrtf((float)(g_cnt[i] + 1));
}

// ---------------- W split halves (coalesced reads, scattered 4B writes) ----------
__global__ void k_splitw_g(const float* __restrict__ Wg) {
    int idx = blockIdx.x * blockDim.x + threadIdx.x;
    if (idx >= 8192) return;
    int n   = idx & 127;
    int kpi = idx >> 7;
    int kp  = kpi * 2;
    int o   = n * 64 + kpi;
    uint32_t phi, plo;
    split2(Wg[kp * 128 + n], Wg[(kp + 1) * 128 + n], phi, plo);
    g_Bg_hi[o] = phi; g_Bg_lo[o] = plo;
}

__global__ void k_splitw_1(const float* __restrict__ W1) {
    int idx = blockIdx.x * blockDim.x + threadIdx.x;
    if (idx >= 8192) return;
    int n   = idx & 127;
    int kpi = idx >> 7;
    int kp  = kpi * 2;
    int o   = n * 64 + kpi;
    uint32_t phi, plo;
    split2(W1[kp * 128 + n], W1[(kp + 1) * 128 + n], phi, plo);
    g_B1_hi[o] = phi; g_B1_lo[o] = plo;
}

// ---------------- B planes -> smem --------------------------------------------------
__device__ __forceinline__ void load_B(char* smem, const uint32_t* __restrict__ bh,
                                       const uint32_t* __restrict__ bl, int tid) {
    uint32_t* BH = (uint32_t*)(smem + SM_BH);
    uint32_t* BL = (uint32_t*)(smem + SM_BL);
    #pragma unroll
    for (int i = tid; i < 8192; i += 256) {
        int n = i >> 6, w = i & 63;
        BH[n * PITCHW + w] = bh[n * 64 + w];
        BL[n * PITCHW + w] = bl[n * 64 + w];
    }
}

// 3-pass split mma (R11-exact). A straight from gmem, split in registers;
// B hi/lo from smem. acc[16][4]; warp = rows [wid*16, wid*16+16).
__device__ __forceinline__ void run_mma_g(char* smem, const float* __restrict__ src,
                                          int row0, float acc[16][4],
                                          int wid, int lane) {
    const uint32_t* BH = (const uint32_t*)(smem + SM_BH);
    const uint32_t* BL = (const uint32_t*)(smem + SM_BL);
    const int gid = lane >> 2;
    const int tig = lane & 3;
    const int rA  = wid * 16 + gid;
    const int gr0 = row0 + rA;
    const int gr1 = gr0 + 8;
    const float* p0 = src + (size_t)(gr0 < NN ? gr0 : row0) * 128;
    const float* p1 = src + (size_t)(gr1 < NN ? gr1 : row0) * 128;

    #pragma unroll 2
    for (int ks = 0; ks < 8; ++ks) {
        const int kw = ks * 8 + tig;
        float2 x0 = *(const float2*)(p0 + 2 * kw);
        float2 x1 = *(const float2*)(p1 + 2 * kw);
        float2 x2 = *(const float2*)(p0 + 2 * kw + 8);
        float2 x3 = *(const float2*)(p1 + 2 * kw + 8);
        uint32_t ah[4], al[4];
        split2(x0.x, x0.y, ah[0], al[0]);
        split2(x1.x, x1.y, ah[1], al[1]);
        split2(x2.x, x2.y, ah[2], al[2]);
        split2(x3.x, x3.y, ah[3], al[3]);
        #pragma unroll
        for (int nf = 0; nf < 16; ++nf) {
            int nB = nf * 8 + gid;
            uint32_t bh0 = BH[nB * PITCHW + kw];
            uint32_t bh1 = BH[nB * PITCHW + kw + 4];
            uint32_t bl0 = BL[nB * PITCHW + kw];
            uint32_t bl1 = BL[nB * PITCHW + kw + 4];
            mma16816(acc[nf], ah, bh0, bh1);
            mma16816(acc[nf], ah, bl0, bl1);
            mma16816(acc[nf], al, bh0, bh1);
        }
    }
}

// ---------------- GEMM1 (tensor, persistent): h = x @ W_gcn (unscaled) -----------
__global__ void __launch_bounds__(256) k_gemm1_tc(const float* __restrict__ x) {
    extern __shared__ char smem[];
    const int tid = threadIdx.x, wid = tid >> 5, lane = tid & 31;

    load_B(smem, g_Bg_hi, g_Bg_lo, tid);
    __syncthreads();

    for (int tile = blockIdx.x; tile < NT; tile += gridDim.x) {
        const int row0 = tile * 128;

        float acc[16][4];
        #pragma unroll
        for (int i = 0; i < 16; ++i)
            acc[i][0] = acc[i][1] = acc[i][2] = acc[i][3] = 0.f;
        run_mma_g(smem, x, row0, acc, wid, lane);

        const int gid = lane >> 2, tig = lane & 3;
        int gr0 = row0 + wid * 16 + gid;
        int gr1 = gr0 + 8;
        float* hf = (float*)g_h;
        #pragma unroll
        for (int nf = 0; nf < 16; ++nf) {
            int c = nf * 8 + tig * 2;
            if (gr0 < NN)
                *(float2*)(hf + (size_t)gr0 * 128 + c) = make_float2(acc[nf][0], acc[nf][1]);
            if (gr1 < NN)
                *(float2*)(hf + (size_t)gr1 * 128 + c) = make_float2(acc[nf][2], acc[nf][3]);
        }
    }
}

// ---------------- gather: agg[d] = relu(dv_d*(dv_d*h[d] + sum dv_s*h[s]) + bg) ---
__global__ void __launch_bounds__(256) k_gather(const float* __restrict__ bg) {
    int gw   = (blockIdx.x * blockDim.x + threadIdx.x) >> 5;
    int lane = threadIdx.x & 31;
    if (gw >= NN) return;
    const int d = gw;

    int deg = g_cnt[d];
    float dv_d = g_dinv[d];
    if (deg > CAP) deg = CAP;

    float4 hd = g_h[d * 32 + lane];
    float4 a0, a1;
    a0.x = hd.x * dv_d; a0.y = hd.y * dv_d; a0.z = hd.z * dv_d; a0.w = hd.w * dv_d;
    a1 = make_float4(0.f, 0.f, 0.f, 0.f);

    const int* bkt = &g_bucket[d * CAP];
    for (int j0 = 0; j0 < deg; j0 += 32) {
        int myi = j0 + lane;
        int   s  = (myi < deg) ? bkt[myi] : 0;
        float nm = (myi < deg) ? g_dinv[s] : 0.f;
        int cnt = deg - j0; if (cnt > 32) cnt = 32;
        int t = 0;
        for (; t + 4 <= cnt; t += 4) {
            int s0 = __shfl_sync(0xFFFFFFFFu, s, t);
            int s1 = __shfl_sync(0xFFFFFFFFu, s, t + 1);
            int s2 = __shfl_sync(0xFFFFFFFFu, s, t + 2);
            int s3 = __shfl_sync(0xFFFFFFFFu, s, t + 3);
            float n0 = __shfl_sync(0xFFFFFFFFu, nm, t);
            float n1 = __shfl_sync(0xFFFFFFFFu, nm, t + 1);
            float n2 = __shfl_sync(0xFFFFFFFFu, nm, t + 2);
            float n3 = __shfl_sync(0xFFFFFFFFu, nm, t + 3);
            float4 v0 = g_h[s0 * 32 + lane];
            float4 v1 = g_h[s1 * 32 + lane];
            float4 v2 = g_h[s2 * 32 + lane];
            float4 v3 = g_h[s3 * 32 + lane];
            a0.x = fmaf(v0.x, n0, a0.x); a0.y = fmaf(v0.y, n0, a0.y);
            a0.z = fmaf(v0.z, n0, a0.z); a0.w = fmaf(v0.w, n0, a0.w);
            a1.x = fmaf(v1.x, n1, a1.x); a1.y = fmaf(v1.y, n1, a1.y);
            a1.z = fmaf(v1.z, n1, a1.z); a1.w = fmaf(v1.w, n1, a1.w);
            a0.x = fmaf(v2.x, n2, a0.x); a0.y = fmaf(v2.y, n2, a0.y);
            a0.z = fmaf(v2.z, n2, a0.z); a0.w = fmaf(v2.w, n2, a0.w);
            a1.x = fmaf(v3.x, n3, a1.x); a1.y = fmaf(v3.y, n3, a1.y);
            a1.z = fmaf(v3.z, n3, a1.z); a1.w = fmaf(v3.w, n3, a1.w);
        }
        for (; t < cnt; ++t) {
            int   ss = __shfl_sync(0xFFFFFFFFu, s, t);
            float nn = __shfl_sync(0xFFFFFFFFu, nm, t);
            float4 v = g_h[ss * 32 + lane];
            a0.x = fmaf(v.x, nn, a0.x); a0.y = fmaf(v.y, nn, a0.y);
            a0.z = fmaf(v.z, nn, a0.z); a0.w = fmaf(v.w, nn, a0.w);
        }
    }
    a0.x += a1.x; a0.y += a1.y; a0.z += a1.z; a0.w += a1.w;

    float4 bgv = __ldg(&((const float4*)bg)[lane]);
    float4 r;
    r.x = fmaxf(fmaf(a0.x, dv_d, bgv.x), 0.f);
    r.y = fmaxf(fmaf(a0.y, dv_d, bgv.y), 0.f);
    r.z = fmaxf(fmaf(a0.z, dv_d, bgv.z), 0.f);
    r.w = fmaxf(fmaf(a0.w, dv_d, bgv.w), 0.f);
    g_agg[d * 32 + lane] = r;
}

// ---------------- MLP (tensor, persistent): out = relu(agg@W1+b1).W2 + b2 --------
__global__ void __launch_bounds__(256) k_mlp_tc(const float* __restrict__ b1,
                                                const float* __restrict__ W2,
                                                const float* __restrict__ b2,
                                                float* __restrict__ out) {
    extern __shared__ char smem[];
    const int tid = threadIdx.x, wid = tid >> 5, lane = tid & 31;

    load_B(smem, g_B1_hi, g_B1_lo, tid);
    __syncthreads();

    for (int tile = blockIdx.x; tile < NT; tile += gridDim.x) {
        const int row0 = tile * 128;

        float acc[16][4];
        #pragma unroll
        for (int i = 0; i < 16; ++i)
            acc[i][0] = acc[i][1] = acc[i][2] = acc[i][3] = 0.f;
        run_mma_g(smem, (const float*)g_agg, row0, acc, wid, lane);

        float sumA = 0.f, sumB = 0.f;
        const int cb = (lane & 3) * 2;
        #pragma unroll
        for (int nf = 0; nf < 16; ++nf) {
            int c = nf * 8 + cb;
            float bb0 = __ldg(b1 + c), bb1 = __ldg(b1 + c + 1);
            float w0  = __ldg(W2 + c), w1  = __ldg(W2 + c + 1);
            sumA = fmaf(fmaxf(acc[nf][0] + bb0, 0.f), w0, sumA);
            sumA = fmaf(fmaxf(acc[nf][1] + bb1, 0.f), w1, sumA);
            sumB = fmaf(fmaxf(acc[nf][2] + bb0, 0.f), w0, sumB);
            sumB = fmaf(fmaxf(acc[nf][3] + bb1, 0.f), w1, sumB);
        }
        sumA += __shfl_xor_sync(0xFFFFFFFFu, sumA, 1);
        sumA += __shfl_xor_sync(0xFFFFFFFFu, sumA, 2);
        sumB += __shfl_xor_sync(0xFFFFFFFFu, sumB, 1);
        sumB += __shfl_xor_sync(0xFFFFFFFFu, sumB, 2);

        if ((lane & 3) == 0) {
            float b2s = __ldg(b2);
            int r = row0 + wid * 16 + (lane >> 2);
            if (r < NN)     out[r]     = sumA + b2s;
            if (r + 8 < NN) out[r + 8] = sumB + b2s;
        }
    }
}

// ---------------- launch -----------------------------------------------------------
extern "C" void kernel_launch(void* const* d_in, const int* in_sizes, int n_in,
                              void* d_out, int out_size) {
    const float* x  = (const float*)d_in[0];
    const int*   ei = (const int*)  d_in[1];
    const float* Wg = (const float*)d_in[2];
    const float* bg = (const float*)d_in[3];
    const float* W1 = (const float*)d_in[4];
    const float* b1 = (const float*)d_in[5];
    const float* W2 = (const float*)d_in[6];
    const float* b2 = (const float*)d_in[7];
    float* out = (float*)d_out;

    cudaFuncSetAttribute(k_gemm1_tc, cudaFuncAttributeMaxDynamicSharedMemorySize, SMEM_BYTES);
    cudaFuncSetAttribute(k_mlp_tc,   cudaFuncAttributeMaxDynamicSharedMemorySize, SMEM_BYTES);

    // streams/events created once on the first (non-captured) correctness call
    static cudaStream_t s1 = nullptr;
    static cudaEvent_t  evF = nullptr, evJ = nullptr;
    if (s1 == nullptr) {
        if (cudaStreamCreateWithFlags(&s1, cudaStreamNonBlocking) != cudaSuccess) s1 = nullptr;
        if (s1 && cudaEventCreateWithFlags(&evF, cudaEventDisableTiming) != cudaSuccess) { evF = nullptr; }
        if (s1 && evF && cudaEventCreateWithFlags(&evJ, cudaEventDisableTiming) != cudaSuccess) { evJ = nullptr; }
    }
    const bool par = (s1 != nullptr) && (evF != nullptr) && (evJ != nullptr);

    if (par) {
        // hidden branch: graph prep + W1 split (only needed by the final MLP)
        cudaEventRecord(evF, 0);
        cudaStreamWaitEvent(s1, evF, 0);
        k_init    <<<(NN + 255) / 256, 256, 0, s1>>>();
        k_fill    <<<(EE / 4 + 255) / 256, 256, 0, s1>>>(ei);
        k_dinv    <<<(NN + 255) / 256, 256, 0, s1>>>();
        k_splitw_1<<<32, 256, 0, s1>>>(W1);
        cudaEventRecord(evJ, s1);
        // critical path
        k_splitw_g<<<32, 256>>>(Wg);
        k_gemm1_tc<<<GRID_P, 256, SMEM_BYTES>>>(x);
        cudaStreamWaitEvent(0, evJ, 0);
    } else {
        k_init    <<<(NN + 255) / 256, 256>>>();
        k_fill    <<<(EE / 4 + 255) / 256, 256>>>(ei);
        k_dinv    <<<(NN + 255) / 256, 256>>>();
        k_splitw_1<<<32, 256>>>(W1);
        k_splitw_g<<<32, 256>>>(Wg);
        k_gemm1_tc<<<GRID_P, 256, SMEM_BYTES>>>(x);
    }

    k_gather<<<(NN * 32 + 255) / 256, 256>>>(bg);
    k_mlp_tc<<<GRID_P, 256, SMEM_BYTES>>>(b1, W2, b2, out);
}

// round 16
// speedup vs baseline: 1.0535x; 1.0069x over previous
#include <cuda_runtime.h>
#include <cuda_bf16.h>
#include <cstdint>

#define NN 50000
#define EE 800000
#define CAP 64            // deg ~ Poisson(16); P(deg>=64) ~ 1e-20
#define NT  391           // ceil(NN/128) tiles
#define GRID_P 296        // persistent grid: 2 CTAs/SM x 148 SMs

// B planes: fragment-major packed uint4 per (nf, ks, lane):
//   g_B[((nf*8+ks)*32 + lane)] = {bh0, bh1, bl0, bl1}
// where gid=lane>>2, tig=lane&3, nB=nf*8+gid, kw=ks*8+tig,
//   bh0/bl0 = hi/lo bf16x2 of W cols (2kw,2kw+1) row nB (transposed),
//   bh1/bl1 = same for (2kw+8, 2kw+9).
#define SMEM_BYTES 65536

// ---------------- scratch (device globals; no allocation allowed) ------------
__device__ int      g_cnt[NN];
__device__ float    g_dinv[NN];
__device__ float4   g_h[NN * 32];         // h = x @ W_gcn (UNSCALED)
__device__ float4   g_agg[NN * 32];       // relu(agg + b_gcn)
__device__ int      g_bucket[NN * CAP];
__device__ uint4    g_Bg[4096];           // W_gcn fragments
__device__ uint4    g_B1[4096];           // W1 fragments

// ---------------- helpers -------------------------------------------------------
__device__ __forceinline__ uint32_t pack_bf2(__nv_bfloat16 lo, __nv_bfloat16 hi) {
    return ((uint32_t)__bfloat16_as_ushort(hi) << 16) | (uint32_t)__bfloat16_as_ushort(lo);
}
__device__ __forceinline__ void split2(float a0, float a1, uint32_t& phi, uint32_t& plo) {
    __nv_bfloat16 h0 = __float2bfloat16_rn(a0);
    __nv_bfloat16 h1 = __float2bfloat16_rn(a1);
    __nv_bfloat16 l0 = __float2bfloat16_rn(a0 - __bfloat162float(h0));
    __nv_bfloat16 l1 = __float2bfloat16_rn(a1 - __bfloat162float(h1));
    phi = pack_bf2(h0, h1);
    plo = pack_bf2(l0, l1);
}
__device__ __forceinline__ void mma16816(float* c, const uint32_t* a,
                                         uint32_t b0, uint32_t b1) {
    asm volatile(
        "mma.sync.aligned.m16n8k16.row.col.f32.bf16.bf16.f32 "
        "{%0,%1,%2,%3}, {%4,%5,%6,%7}, {%8,%9}, {%0,%1,%2,%3};"
        : "+f"(c[0]), "+f"(c[1]), "+f"(c[2]), "+f"(c[3])
        : "r"(a[0]), "r"(a[1]), "r"(a[2]), "r"(a[3]), "r"(b0), "r"(b1));
}

// ---------------- bucket build ---------------------------------------------------
__global__ void k_init() {
    int i = blockIdx.x * blockDim.x + threadIdx.x;
    if (i < NN) g_cnt[i] = 0;
}

__global__ void k_fill(const int* __restrict__ ei) {
    int e4 = blockIdx.x * blockDim.x + threadIdx.x;
    if (e4 >= EE / 4) return;
    int4 s = ((const int4*)ei)[e4];
    int4 d = ((const int4*)(ei + EE))[e4];
    int p;
    p = atomicAdd(&g_cnt[d.x], 1); if (p < CAP) g_bucket[d.x * CAP + p] = s.x;
    p = atomicAdd(&g_cnt[d.y], 1); if (p < CAP) g_bucket[d.y * CAP + p] = s.y;
    p = atomicAdd(&g_cnt[d.z], 1); if (p < CAP) g_bucket[d.z * CAP + p] = s.z;
    p = atomicAdd(&g_cnt[d.w], 1); if (p < CAP) g_bucket[d.w * CAP + p] = s.w;
}

__global__ void k_dinv() {
    int i = blockIdx.x * blockDim.x + threadIdx.x;
    if (i < NN) g_dinv[i] = rsqrtf((float)(g_cnt[i] + 1));
}

// ---------------- W split -> fragment-major packed layout ------------------------
__device__ __forceinline__ void splitw_one(const float* __restrict__ W,
                                           uint4* __restrict__ dst, int idx) {
    int lane = idx & 31;
    int ks   = (idx >> 5) & 7;
    int nf   = idx >> 8;
    int gid = lane >> 2, tig = lane & 3;
    int nB = nf * 8 + gid;
    int kw = ks * 8 + tig;
    uint32_t bh0, bl0, bh1, bl1;
    split2(W[(2 * kw)     * 128 + nB], W[(2 * kw + 1) * 128 + nB], bh0, bl0);
    split2(W[(2 * kw + 8) * 128 + nB], W[(2 * kw + 9) * 128 + nB], bh1, bl1);
    dst[idx] = make_uint4(bh0, bh1, bl0, bl1);
}

__global__ void k_splitw_g(const float* __restrict__ Wg) {
    int idx = blockIdx.x * blockDim.x + threadIdx.x;
    if (idx < 4096) splitw_one(Wg, g_Bg, idx);
}
__global__ void k_splitw_1(const float* __restrict__ W1) {
    int idx = blockIdx.x * blockDim.x + threadIdx.x;
    if (idx < 4096) splitw_one(W1, g_B1, idx);
}

// ---------------- B fragments -> smem (plain uint4 copy) --------------------------
__device__ __forceinline__ void load_B(char* smem, const uint4* __restrict__ src, int tid) {
    uint4* dst = (uint4*)smem;
    #pragma unroll
    for (int i = tid; i < 4096; i += 256) dst[i] = src[i];
}

// 3-pass split mma. A straight from gmem, split in registers; B fragments via
// single LDS.128 per (nf, ks). acc[16][4]; warp = rows [wid*16, wid*16+16).
__device__ __forceinline__ void run_mma_g(char* smem, const float* __restrict__ src,
                                          int row0, float acc[16][4],
                                          int wid, int lane) {
    const uint4* BF = (const uint4*)smem;
    const int gid = lane >> 2;
    const int tig = lane & 3;
    const int rA  = wid * 16 + gid;
    const int gr0 = row0 + rA;
    const int gr1 = gr0 + 8;
    const float* p0 = src + (size_t)(gr0 < NN ? gr0 : row0) * 128;
    const float* p1 = src + (size_t)(gr1 < NN ? gr1 : row0) * 128;

    #pragma unroll 2
    for (int ks = 0; ks < 8; ++ks) {
        const int kw = ks * 8 + tig;
        float2 x0 = *(const float2*)(p0 + 2 * kw);
        float2 x1 = *(const float2*)(p1 + 2 * kw);
        float2 x2 = *(const float2*)(p0 + 2 * kw + 8);
        float2 x3 = *(const float2*)(p1 + 2 * kw + 8);
        uint32_t ah[4], al[4];
        split2(x0.x, x0.y, ah[0], al[0]);
        split2(x1.x, x1.y, ah[1], al[1]);
        split2(x2.x, x2.y, ah[2], al[2]);
        split2(x3.x, x3.y, ah[3], al[3]);
        #pragma unroll
        for (int nf = 0; nf < 16; ++nf) {
            uint4 b = BF[(nf * 8 + ks) * 32 + lane];
            mma16816(acc[nf], ah, b.x, b.y);   // A_hi * B_hi
            mma16816(acc[nf], ah, b.z, b.w);   // A_hi * B_lo
            mma16816(acc[nf], al, b.x, b.y);   // A_lo * B_hi
        }
    }
}

// ---------------- GEMM1 (tensor, persistent): h = x @ W_gcn (unscaled) -----------
__global__ void __launch_bounds__(256) k_gemm1_tc(const float* __restrict__ x) {
    extern __shared__ char smem[];
    const int tid = threadIdx.x, wid = tid >> 5, lane = tid & 31;

    load_B(smem, g_Bg, tid);
    __syncthreads();

    for (int tile = blockIdx.x; tile < NT; tile += gridDim.x) {
        const int row0 = tile * 128;

        float acc[16][4];
        #pragma unroll
        for (int i = 0; i < 16; ++i)
            acc[i][0] = acc[i][1] = acc[i][2] = acc[i][3] = 0.f;
        run_mma_g(smem, x, row0, acc, wid, lane);

        const int gid = lane >> 2, tig = lane & 3;
        int gr0 = row0 + wid * 16 + gid;
        int gr1 = gr0 + 8;
        float* hf = (float*)g_h;
        #pragma unroll
        for (int nf = 0; nf < 16; ++nf) {
            int c = nf * 8 + tig * 2;
            if (gr0 < NN)
                *(float2*)(hf + (size_t)gr0 * 128 + c) = make_float2(acc[nf][0], acc[nf][1]);
            if (gr1 < NN)
                *(float2*)(hf + (size_t)gr1 * 128 + c) = make_float2(acc[nf][2], acc[nf][3]);
        }
    }
}

// ---------------- gather: agg[d] = relu(dv_d*(dv_d*h[d] + sum dv_s*h[s]) + bg) ---
__global__ void __launch_bounds__(256) k_gather(const float* __restrict__ bg) {
    int gw   = (blockIdx.x * blockDim.x + threadIdx.x) >> 5;
    int lane = threadIdx.x & 31;
    if (gw >= NN) return;
    const int d = gw;

    int deg = g_cnt[d];
    float dv_d = g_dinv[d];
    if (deg > CAP) deg = CAP;

    float4 hd = g_h[d * 32 + lane];
    float4 a0, a1;
    a0.x = hd.x * dv_d; a0.y = hd.y * dv_d; a0.z = hd.z * dv_d; a0.w = hd.w * dv_d;
    a1 = make_float4(0.f, 0.f, 0.f, 0.f);

    const int* bkt = &g_bucket[d * CAP];
    for (int j0 = 0; j0 < deg; j0 += 32) {
        int myi = j0 + lane;
        int   s  = (myi < deg) ? bkt[myi] : 0;
        float nm = (myi < deg) ? g_dinv[s] : 0.f;
        int cnt = deg - j0; if (cnt > 32) cnt = 32;
        int t = 0;
        for (; t + 4 <= cnt; t += 4) {
            int s0 = __shfl_sync(0xFFFFFFFFu, s, t);
            int s1 = __shfl_sync(0xFFFFFFFFu, s, t + 1);
            int s2 = __shfl_sync(0xFFFFFFFFu, s, t + 2);
            int s3 = __shfl_sync(0xFFFFFFFFu, s, t + 3);
            float n0 = __shfl_sync(0xFFFFFFFFu, nm, t);
            float n1 = __shfl_sync(0xFFFFFFFFu, nm, t + 1);
            float n2 = __shfl_sync(0xFFFFFFFFu, nm, t + 2);
            float n3 = __shfl_sync(0xFFFFFFFFu, nm, t + 3);
            float4 v0 = g_h[s0 * 32 + lane];
            float4 v1 = g_h[s1 * 32 + lane];
            float4 v2 = g_h[s2 * 32 + lane];
            float4 v3 = g_h[s3 * 32 + lane];
            a0.x = fmaf(v0.x, n0, a0.x); a0.y = fmaf(v0.y, n0, a0.y);
            a0.z = fmaf(v0.z, n0, a0.z); a0.w = fmaf(v0.w, n0, a0.w);
            a1.x = fmaf(v1.x, n1, a1.x); a1.y = fmaf(v1.y, n1, a1.y);
            a1.z = fmaf(v1.z, n1, a1.z); a1.w = fmaf(v1.w, n1, a1.w);
            a0.x = fmaf(v2.x, n2, a0.x); a0.y = fmaf(v2.y, n2, a0.y);
            a0.z = fmaf(v2.z, n2, a0.z); a0.w = fmaf(v2.w, n2, a0.w);
            a1.x = fmaf(v3.x, n3, a1.x); a1.y = fmaf(v3.y, n3, a1.y);
            a1.z = fmaf(v3.z, n3, a1.z); a1.w = fmaf(v3.w, n3, a1.w);
        }
        for (; t < cnt; ++t) {
            int   ss = __shfl_sync(0xFFFFFFFFu, s, t);
            float nn = __shfl_sync(0xFFFFFFFFu, nm, t);
            float4 v = g_h[ss * 32 + lane];
            a0.x = fmaf(v.x, nn, a0.x); a0.y = fmaf(v.y, nn, a0.y);
            a0.z = fmaf(v.z, nn, a0.z); a0.w = fmaf(v.w, nn, a0.w);
        }
    }
    a0.x += a1.x; a0.y += a1.y; a0.z += a1.z; a0.w += a1.w;

    float4 bgv = __ldg(&((const float4*)bg)[lane]);
    float4 r;
    r.x = fmaxf(fmaf(a0.x, dv_d, bgv.x), 0.f);
    r.y = fmaxf(fmaf(a0.y, dv_d, bgv.y), 0.f);
    r.z = fmaxf(fmaf(a0.z, dv_d, bgv.z), 0.f);
    r.w = fmaxf(fmaf(a0.w, dv_d, bgv.w), 0.f);
    g_agg[d * 32 + lane] = r;
}

// ---------------- MLP (tensor, persistent): out = relu(agg@W1+b1).W2 + b2 --------
__global__ void __launch_bounds__(256) k_mlp_tc(const float* __restrict__ b1,
                                                const float* __restrict__ W2,
                                                const float* __restrict__ b2,
                                                float* __restrict__ out) {
    extern __shared__ char smem[];
    const int tid = threadIdx.x, wid = tid >> 5, lane = tid & 31;

    load_B(smem, g_B1, tid);
    __syncthreads();

    for (int tile = blockIdx.x; tile < NT; tile += gridDim.x) {
        const int row0 = tile * 128;

        float acc[16][4];
        #pragma unroll
        for (int i = 0; i < 16; ++i)
            acc[i][0] = acc[i][1] = acc[i][2] = acc[i][3] = 0.f;
        run_mma_g(smem, (const float*)g_agg, row0, acc, wid, lane);

        float sumA = 0.f, sumB = 0.f;
        const int cb = (lane & 3) * 2;
        #pragma unroll
        for (int nf = 0; nf < 16; ++nf) {
            int c = nf * 8 + cb;
            float bb0 = __ldg(b1 + c), bb1 = __ldg(b1 + c + 1);
            float w0  = __ldg(W2 + c), w1  = __ldg(W2 + c + 1);
            sumA = fmaf(fmaxf(acc[nf][0] + bb0, 0.f), w0, sumA);
            sumA = fmaf(fmaxf(acc[nf][1] + bb1, 0.f), w1, sumA);
            sumB = fmaf(fmaxf(acc[nf][2] + bb0, 0.f), w0, sumB);
            sumB = fmaf(fmaxf(acc[nf][3] + bb1, 0.f), w1, sumB);
        }
        sumA += __shfl_xor_sync(0xFFFFFFFFu, sumA, 1);
        sumA += __shfl_xor_sync(0xFFFFFFFFu, sumA, 2);
        sumB += __shfl_xor_sync(0xFFFFFFFFu, sumB, 1);
        sumB += __shfl_xor_sync(0xFFFFFFFFu, sumB, 2);

        if ((lane & 3) == 0) {
            float b2s = __ldg(b2);
            int r = row0 + wid * 16 + (lane >> 2);
            if (r < NN)     out[r]     = sumA + b2s;
            if (r + 8 < NN) out[r + 8] = sumB + b2s;
        }
    }
}

// ---------------- launch -----------------------------------------------------------
extern "C" void kernel_launch(void* const* d_in, const int* in_sizes, int n_in,
                              void* d_out, int out_size) {
    const float* x  = (const float*)d_in[0];
    const int*   ei = (const int*)  d_in[1];
    const float* Wg = (const float*)d_in[2];
    const float* bg = (const float*)d_in[3];
    const float* W1 = (const float*)d_in[4];
    const float* b1 = (const float*)d_in[5];
    const float* W2 = (const float*)d_in[6];
    const float* b2 = (const float*)d_in[7];
    float* out = (float*)d_out;

    cudaFuncSetAttribute(k_gemm1_tc, cudaFuncAttributeMaxDynamicSharedMemorySize, SMEM_BYTES);
    cudaFuncSetAttribute(k_mlp_tc,   cudaFuncAttributeMaxDynamicSharedMemorySize, SMEM_BYTES);

    // streams/events created once on the first (non-captured) correctness call
    static cudaStream_t s1 = nullptr;
    static cudaEvent_t  evF = nullptr, evJ = nullptr;
    if (s1 == nullptr) {
        if (cudaStreamCreateWithFlags(&s1, cudaStreamNonBlocking) != cudaSuccess) s1 = nullptr;
        if (s1 && cudaEventCreateWithFlags(&evF, cudaEventDisableTiming) != cudaSuccess) { evF = nullptr; }
        if (s1 && evF && cudaEventCreateWithFlags(&evJ, cudaEventDisableTiming) != cudaSuccess) { evJ = nullptr; }
    }
    const bool par = (s1 != nullptr) && (evF != nullptr) && (evJ != nullptr);

    if (par) {
        cudaEventRecord(evF, 0);
        cudaStreamWaitEvent(s1, evF, 0);
        k_init    <<<(NN + 255) / 256, 256, 0, s1>>>();
        k_fill    <<<(EE / 4 + 255) / 256, 256, 0, s1>>>(ei);
        k_dinv    <<<(NN + 255) / 256, 256, 0, s1>>>();
        k_splitw_1<<<16, 256, 0, s1>>>(W1);
        cudaEventRecord(evJ, s1);
        k_splitw_g<<<16, 256>>>(Wg);
        k_gemm1_tc<<<GRID_P, 256, SMEM_BYTES>>>(x);
        cudaStreamWaitEvent(0, evJ, 0);
    } else {
        k_init    <<<(NN + 255) / 256, 256>>>();
        k_fill    <<<(EE / 4 + 255) / 256, 256>>>(ei);
        k_dinv    <<<(NN + 255) / 256, 256>>>();
        k_splitw_1<<<16, 256>>>(W1);
        k_splitw_g<<<16, 256>>>(Wg);
        k_gemm1_tc<<<GRID_P, 256, SMEM_BYTES>>>(x);
    }

    k_gather<<<(NN * 32 + 255) / 256, 256>>>(bg);
    k_mlp_tc<<<GRID_P, 256, SMEM_BYTES>>>(b1, W2, b2, out);
}